// round 15
// baseline (speedup 1.0000x reference)
#include <cuda_runtime.h>
#include <cuda_fp16.h>
#include <cstdint>

#define EPSBN 1e-5f
#define B_  16384
#define D0  784
#define K1  832
#define D1  3072
#define D2  1536
#define D3  768
#define D4  10
#define TAU 0.03f
#define FIXCAP (1 << 21)

__device__ __align__(128) __half d_A1[(size_t)B_*K1];
__device__ __align__(128) __half d_B1[(size_t)D1*K1];
__device__ __align__(128) __half d_B2[(size_t)D2*D1];
__device__ __align__(128) __half d_B3[(size_t)D3*D2];
__device__ __align__(128) __half d_act1[(size_t)B_*D1];
__device__ __align__(128) __half d_act2[(size_t)B_*D2];
__device__ __align__(128) float d_h3c[(size_t)B_*D3];
__device__ float d_thr1[D1], d_sg1[D1], d_thr2[D2], d_sg2[D2], d_s3[D3], d_o3[D3];
__device__ int d_fix_cnt;
__device__ int d_fix_list[FIXCAP];

__device__ __forceinline__ uint32_t smem_u32(const void* p) {
    uint32_t a;
    asm("{ .reg .u64 t; cvta.to.shared.u64 t, %1; cvt.u32.u64 %0, t; }" : "=r"(a) : "l"(p));
    return a;
}
#define CPA16(dst, src) asm volatile("cp.async.cg.shared.global [%0], [%1], 16;" :: "r"(dst), "l"(src) : "memory")
#define CPA_COMMIT()    asm volatile("cp.async.commit_group;" ::: "memory")
#define CPA_WAIT1()     asm volatile("cp.async.wait_group 1;" ::: "memory")

__device__ __forceinline__ void ldm4(uint32_t* r, uint32_t a) {
    asm volatile("ldmatrix.sync.aligned.m8n8.x4.shared.b16 {%0,%1,%2,%3}, [%4];"
                 : "=r"(r[0]), "=r"(r[1]), "=r"(r[2]), "=r"(r[3]) : "r"(a));
}
__device__ __forceinline__ void mma_f16(float* c, const uint32_t* a, const uint32_t* b) {
    asm volatile("mma.sync.aligned.m16n8k16.row.col.f32.f16.f16.f32 "
                 "{%0,%1,%2,%3}, {%4,%5,%6,%7}, {%8,%9}, {%0,%1,%2,%3};"
                 : "+f"(c[0]), "+f"(c[1]), "+f"(c[2]), "+f"(c[3])
                 : "r"(a[0]), "r"(a[1]), "r"(a[2]), "r"(a[3]), "r"(b[0]), "r"(b[1]));
}
// f16 accumulator: exact for integer sums |s| <= 2048
__device__ __forceinline__ void mma_f16h(uint32_t* c, const uint32_t* a, const uint32_t* b) {
    asm volatile("mma.sync.aligned.m16n8k16.row.col.f16.f16.f16.f16 "
                 "{%0,%1}, {%2,%3,%4,%5}, {%6,%7}, {%0,%1};"
                 : "+r"(c[0]), "+r"(c[1])
                 : "r"(a[0]), "r"(a[1]), "r"(a[2]), "r"(a[3]), "r"(b[0]), "r"(b[1]));
}

__device__ __forceinline__ float sgnf(float w) {
    return (w > 0.f) ? 1.f : ((w < 0.f) ? -1.f : 0.f);
}
__device__ __forceinline__ void st4h(__half* p, float a, float b, float c, float d) {
    __half2 lo = __floats2half2_rn(a, b);
    __half2 hi = __floats2half2_rn(c, d);
    uint2 u;
    u.x = *(uint32_t*)&lo;
    u.y = *(uint32_t*)&hi;
    *(uint2*)p = u;
}

// ---------------- merged prep, x4 vectorized (single launch) -------------
#define NA4   ((size_t)B_ * D0 / 4)
#define NPA4  ((size_t)B_ * (K1 - D0) / 4)
#define NB4   ((size_t)D1 * D0 / 4)
#define NPB4  ((size_t)D1 * (K1 - D0) / 4)
#define NW24  ((size_t)D2 * D1 / 4)
#define NW34  ((size_t)D3 * D2 / 4)
#define NTOT4 (NA4 + NPA4 + NB4 + NPB4 + NW24 + NW34 + D1)

__global__ void prep_all(const float* __restrict__ x,  const float* __restrict__ w1,
                         const float* __restrict__ w2, const float* __restrict__ w3,
    const float* __restrict__ b1, const float* __restrict__ g1, const float* __restrict__ be1,
    const float* __restrict__ m1, const float* __restrict__ v1,
    const float* __restrict__ b2, const float* __restrict__ g2, const float* __restrict__ be2,
    const float* __restrict__ m2, const float* __restrict__ v2,
    const float* __restrict__ b3, const float* __restrict__ g3, const float* __restrict__ be3,
    const float* __restrict__ m3, const float* __restrict__ v3)
{
    size_t idx = (size_t)blockIdx.x * 256 + threadIdx.x;
    if (idx == 0) d_fix_cnt = 0;
    if (idx < NA4) {
        int i = (int)(idx / (D0/4)), k4 = (int)(idx % (D0/4));
        float4 v = *(const float4*)(x + (size_t)i * D0 + k4 * 4);
        st4h(d_A1 + (size_t)i * K1 + k4 * 4, v.x, v.y, v.z, v.w);
    } else if (idx < NA4 + NPA4) {
        size_t t = idx - NA4;
        int i = (int)(t / 12), j = (int)(t % 12);
        st4h(d_A1 + (size_t)i * K1 + D0 + j * 4, 0.f, 0.f, 0.f, 0.f);
    } else if (idx < NA4 + NPA4 + NB4) {
        size_t t = idx - NA4 - NPA4;
        int i = (int)(t / (D0/4)), k4 = (int)(t % (D0/4));
        float4 v = *(const float4*)(w1 + (size_t)i * D0 + k4 * 4);
        st4h(d_B1 + (size_t)i * K1 + k4 * 4, sgnf(v.x), sgnf(v.y), sgnf(v.z), sgnf(v.w));
    } else if (idx < NA4 + NPA4 + NB4 + NPB4) {
        size_t t = idx - NA4 - NPA4 - NB4;
        int i = (int)(t / 12), j = (int)(t % 12);
        st4h(d_B1 + (size_t)i * K1 + D0 + j * 4, 0.f, 0.f, 0.f, 0.f);
    } else if (idx < NA4 + NPA4 + NB4 + NPB4 + NW24) {
        size_t t = (idx - NA4 - NPA4 - NB4 - NPB4) * 4;
        float4 v = *(const float4*)(w2 + t);
        st4h(d_B2 + t, sgnf(v.x), sgnf(v.y), sgnf(v.z), sgnf(v.w));
    } else if (idx < NA4 + NPA4 + NB4 + NPB4 + NW24 + NW34) {
        size_t t = (idx - NA4 - NPA4 - NB4 - NPB4 - NW24) * 4;
        float4 v = *(const float4*)(w3 + t);
        st4h(d_B3 + t, sgnf(v.x), sgnf(v.y), sgnf(v.z), sgnf(v.w));
    } else {
        int j = (int)(idx - (NA4 + NPA4 + NB4 + NPB4 + NW24 + NW34));
        if (j < D1) {
            float g = g1[j];
            d_thr1[j] = m1[j] - be1[j] * sqrtf(v1[j] + EPSBN) / g - b1[j];
            d_sg1[j]  = (g > 0.f) ? 1.f : -1.f;
        }
        if (j < D2) {
            float g = g2[j];
            d_thr2[j] = m2[j] - be2[j] * sqrtf(v2[j] + EPSBN) / g - b2[j];
            d_sg2[j]  = (g > 0.f) ? 1.f : -1.f;
        }
        if (j < D3) {
            float g = g3[j];
            float s = g / sqrtf(v3[j] + EPSBN);
            d_s3[j] = s;
            d_o3[j] = (b3[j] - m3[j]) * s + be3[j];
        }
    }
}

// ---------------- repair: warp-cooperative staging, exact sequential sum --
#define RWARPS 4
__global__ __launch_bounds__(128) void repair1(const float* __restrict__ x,
                                               const float* __restrict__ w1) {
    __shared__ float sx[RWARPS][D0];
    __shared__ float sw[RWARPS][D0];
    int cnt = d_fix_cnt; if (cnt > FIXCAP) cnt = FIXCAP;
    int warp = threadIdx.x >> 5, lane = threadIdx.x & 31;
    for (int i = blockIdx.x * RWARPS + warp; i < cnt; i += gridDim.x * RWARPS) {
        int e = d_fix_list[i];
        int m = e / D1, n = e % D1;
        const float* xr = x  + (size_t)m * D0;
        const float* wr = w1 + (size_t)n * D0;
        #pragma unroll 5
        for (int k = lane; k < D0; k += 32) {
            sx[warp][k] = xr[k];
            float w = wr[k];
            sw[warp][k] = (w > 0.f) ? 1.f : ((w < 0.f) ? -1.f : 0.f);
        }
        __syncwarp();
        if (lane == 0) {
            float acc = 0.f;
            for (int k = 0; k < D0; k++)
                acc = fmaf(sx[warp][k], sw[warp][k], acc);
            float f = d_sg1[n] * (acc - d_thr1[n]);
            d_act1[(size_t)m * D1 + n] = __float2half_rn((f > 0.f) ? 1.f : -1.f);
        }
        __syncwarp();
    }
}

// ---------------- fc1 GEMM: f32 acc, 128x128 CTA tile, 3-stage (R10) -----
#define SMEMB 98304

__global__ __launch_bounds__(256, 2) void gemm1k() {
    constexpr int NS = 13, KB = K1*2, NN = D1;
    extern __shared__ char sm[];
    uint32_t sb = smem_u32(sm);
    int tid = threadIdx.x, lane = tid & 31, wid = tid >> 5;
    int wm = wid & 3, wn = wid >> 2;
    int m0 = blockIdx.y * 128, n0 = blockIdx.x * 128;

    const char* gA = (const char*)d_A1;
    const char* gB = (const char*)d_B1;
    int r = tid >> 1, h = tid & 1;
    gA += (size_t)(m0 + r) * KB + h * 64;
    gB += (size_t)(n0 + r) * KB + h * 64;

    auto load = [&](int kt, int s) {
        uint32_t o = sb + s * 32768 + r * 128;
        size_t ko = (size_t)kt * 128;
        #pragma unroll
        for (int j = 0; j < 4; j++) {
            uint32_t sw = (uint32_t)(((h * 4 + j) ^ (r & 7)) << 4);
            CPA16(o + sw,         gA + ko + j * 16);
            CPA16(o + 16384 + sw, gB + ko + j * 16);
        }
    };

    float Cf[2][8][4];
    #pragma unroll
    for (int mt = 0; mt < 2; mt++)
        #pragma unroll
        for (int nt = 0; nt < 8; nt++)
            #pragma unroll
            for (int q = 0; q < 4; q++) Cf[mt][nt][q] = 0.f;

    load(0, 0); CPA_COMMIT();
    load(1, 1); CPA_COMMIT();

    int arow = wm * 32 + (lane & 15);
    int asel = lane >> 4;
    int brow = wn * 64 + (lane & 7) + ((lane >> 4) << 3);
    int bsel = (lane >> 3) & 1;

    for (int kt = 0; kt < NS; ++kt) {
        CPA_WAIT1();
        __syncthreads();
        uint32_t Ab = sb + (kt % 3) * 32768;
        uint32_t Bb = Ab + 16384;
        uint32_t a[2][2][4], b[2][4][4];
        #define LDFRAG(d, kk)                                                        \
            do {                                                                     \
                _Pragma("unroll")                                                    \
                for (int mt = 0; mt < 2; mt++) {                                     \
                    int rr = arow + mt * 16;                                         \
                    ldm4(a[d][mt], Ab + rr * 128 + ((((kk) * 2 + asel) ^ (rr & 7)) << 4)); \
                }                                                                    \
                _Pragma("unroll")                                                    \
                for (int q = 0; q < 4; q++) {                                        \
                    int nr = brow + q * 16;                                          \
                    ldm4(b[d][q], Bb + nr * 128 + ((((kk) * 2 + bsel) ^ (nr & 7)) << 4)); \
                }                                                                    \
            } while (0)
        LDFRAG(0, 0);
        #pragma unroll
        for (int kk = 0; kk < 4; kk++) {
            int cur = kk & 1;
            if (kk < 3) {
                LDFRAG(cur ^ 1, kk + 1);
            } else {
                if (kt + 2 < NS) load(kt + 2, (kt + 2) % 3);
                CPA_COMMIT();
            }
            #pragma unroll
            for (int mt = 0; mt < 2; mt++)
                #pragma unroll
                for (int q = 0; q < 4; q++) {
                    mma_f16(Cf[mt][2*q],     a[cur][mt], &b[cur][q][0]);
                    mma_f16(Cf[mt][2*q + 1], a[cur][mt], &b[cur][q][2]);
                }
        }
        #undef LDFRAG
    }
    __syncthreads();

    int g = lane >> 2, tig = lane & 3;
    const __half POS = __float2half_rn(1.f), NEG = __float2half_rn(-1.f);
    __half* stg = (__half*)sm;
    #pragma unroll
    for (int mt = 0; mt < 2; mt++)
        #pragma unroll
        for (int nt = 0; nt < 8; nt++) {
            int col = wn * 64 + nt * 8 + tig * 2;
            int n = n0 + col;
            float t0 = d_thr1[n], t1 = d_thr1[n+1], s0 = d_sg1[n], s1 = d_sg1[n+1];
            int row0 = wm * 32 + mt * 16 + g;
            float f0 = s0 * (Cf[mt][nt][0] - t0), f1 = s1 * (Cf[mt][nt][1] - t1);
            float f2 = s0 * (Cf[mt][nt][2] - t0), f3 = s1 * (Cf[mt][nt][3] - t1);
            stg[row0 * 128 + col]       = (f0 > 0.f) ? POS : NEG;
            stg[row0 * 128 + col + 1]   = (f1 > 0.f) ? POS : NEG;
            stg[(row0+8) * 128 + col]   = (f2 > 0.f) ? POS : NEG;
            stg[(row0+8) * 128 + col+1] = (f3 > 0.f) ? POS : NEG;
            if (fabsf(f0) < TAU) { int ix = atomicAdd(&d_fix_cnt, 1); if (ix < FIXCAP) d_fix_list[ix] = (m0+row0)   * D1 + n;   }
            if (fabsf(f1) < TAU) { int ix = atomicAdd(&d_fix_cnt, 1); if (ix < FIXCAP) d_fix_list[ix] = (m0+row0)   * D1 + n+1; }
            if (fabsf(f2) < TAU) { int ix = atomicAdd(&d_fix_cnt, 1); if (ix < FIXCAP) d_fix_list[ix] = (m0+row0+8) * D1 + n;   }
            if (fabsf(f3) < TAU) { int ix = atomicAdd(&d_fix_cnt, 1); if (ix < FIXCAP) d_fix_list[ix] = (m0+row0+8) * D1 + n+1; }
        }
    __syncthreads();
    for (int i = tid; i < 2048; i += 256) {
        int row = i >> 4, c = i & 15;
        uint4 v = *(const uint4*)(stg + row * 128 + c * 8);
        *(uint4*)(d_act1 + (size_t)(m0 + row) * NN + n0 + c * 8) = v;
    }
}

// ---------------- fc2/fc3: K-split f16-acc GEMM, CTA 128x128 (R13) -------
template <int LAYER>
__global__ __launch_bounds__(256, 2) void bgemm_k() {
    constexpr int NS = (LAYER == 2) ? 48 : 24;
    constexpr int KB = (LAYER == 2) ? D1*2 : D2*2;
    constexpr int NN = (LAYER == 2) ? D2 : D3;

    extern __shared__ char sm[];
    uint32_t sb = smem_u32(sm);
    int tid = threadIdx.x, lane = tid & 31, wid = tid >> 5;
    int tile = wid & 3, khalf = wid >> 2;
    int wm = tile & 1, wn = tile >> 1;
    int m0 = blockIdx.y * 128, n0 = blockIdx.x * 128;

    const char* gA = (LAYER == 2) ? (const char*)d_act1 : (const char*)d_act2;
    const char* gB = (LAYER == 2) ? (const char*)d_B2   : (const char*)d_B3;
    int r = tid >> 1, h = tid & 1;
    gA += (size_t)(m0 + r) * KB + h * 64;
    gB += (size_t)(n0 + r) * KB + h * 64;

    auto load = [&](int kt, int s) {
        uint32_t o = sb + s * 32768 + r * 128;
        size_t ko = (size_t)kt * 128;
        #pragma unroll
        for (int j = 0; j < 4; j++) {
            uint32_t sw = (uint32_t)(((h * 4 + j) ^ (r & 7)) << 4);
            CPA16(o + sw,         gA + ko + j * 16);
            CPA16(o + 16384 + sw, gB + ko + j * 16);
        }
    };

    uint32_t Ch[4][8][2];
    #pragma unroll
    for (int mt = 0; mt < 4; mt++)
        #pragma unroll
        for (int nt = 0; nt < 8; nt++) { Ch[mt][nt][0] = 0u; Ch[mt][nt][1] = 0u; }

    load(0, 0); CPA_COMMIT();
    load(1, 1); CPA_COMMIT();

    int arow = wm * 64 + (lane & 15);
    int asel = lane >> 4;
    int brow = wn * 64 + (lane & 7) + ((lane >> 4) << 3);
    int bsel = (lane >> 3) & 1;

    for (int kt = 0; kt < NS; ++kt) {
        CPA_WAIT1();
        __syncthreads();
        uint32_t Ab = sb + (kt % 3) * 32768;
        uint32_t Bb = Ab + 16384;
        #pragma unroll
        for (int k2 = 0; k2 < 2; k2++) {
            int kk = khalf * 2 + k2;
            uint32_t a[4][4], b[4][4];
            #pragma unroll
            for (int mt = 0; mt < 4; mt++) {
                int rr = arow + mt * 16;
                ldm4(a[mt], Ab + rr * 128 + (((kk * 2 + asel) ^ (rr & 7)) << 4));
            }
            #pragma unroll
            for (int q = 0; q < 4; q++) {
                int nr = brow + q * 16;
                ldm4(b[q], Bb + nr * 128 + (((kk * 2 + bsel) ^ (nr & 7)) << 4));
            }
            if (k2 == 1) {
                if (kt + 2 < NS) load(kt + 2, (kt + 2) % 3);
                CPA_COMMIT();
            }
            #pragma unroll
            for (int mt = 0; mt < 4; mt++)
                #pragma unroll
                for (int q = 0; q < 4; q++) {
                    mma_f16h(Ch[mt][2*q],     a[mt], &b[q][0]);
                    mma_f16h(Ch[mt][2*q + 1], a[mt], &b[q][2]);
                }
        }
    }
    __syncthreads();   // pipeline smem dead; reuse

    // merge: khalf=1 warps dump partials (32KB at sm+0)
    uint32_t* mrg = (uint32_t*)sm;
    if (khalf == 1) {
        #pragma unroll
        for (int mt = 0; mt < 4; mt++)
            #pragma unroll
            for (int nt = 0; nt < 8; nt++) {
                mrg[tile * 2048 + ((mt*8+nt)*2 + 0) * 32 + lane] = Ch[mt][nt][0];
                mrg[tile * 2048 + ((mt*8+nt)*2 + 1) * 32 + lane] = Ch[mt][nt][1];
            }
    }
    __syncthreads();

    int g = lane >> 2, tig = lane & 3;
    if constexpr (LAYER == 2) {
        const __half POS = __float2half_rn(1.f), NEG = __float2half_rn(-1.f);
        __half* stg = (__half*)(sm + 32768);
        if (khalf == 0) {
            #pragma unroll
            for (int mt = 0; mt < 4; mt++)
                #pragma unroll
                for (int nt = 0; nt < 8; nt++) {
                    int col = wn * 64 + nt * 8 + tig * 2;
                    int n = n0 + col;
                    float t0 = d_thr2[n], t1 = d_thr2[n+1], s0 = d_sg2[n], s1 = d_sg2[n+1];
                    int row0 = wm * 64 + mt * 16 + g;
                    uint32_t p0 = mrg[tile * 2048 + ((mt*8+nt)*2 + 0) * 32 + lane];
                    uint32_t p1 = mrg[tile * 2048 + ((mt*8+nt)*2 + 1) * 32 + lane];
                    float2 m0v = __half22float2(*(const __half2*)&Ch[mt][nt][0]);
                    float2 m1v = __half22float2(*(const __half2*)&Ch[mt][nt][1]);
                    float2 p0v = __half22float2(*(const __half2*)&p0);
                    float2 p1v = __half22float2(*(const __half2*)&p1);
                    float d0 = m0v.x + p0v.x, d1 = m0v.y + p0v.y;
                    float d2 = m1v.x + p1v.x, d3 = m1v.y + p1v.y;
                    stg[row0 * 128 + col]       = (s0 * (d0 - t0) > 0.f) ? POS : NEG;
                    stg[row0 * 128 + col + 1]   = (s1 * (d1 - t1) > 0.f) ? POS : NEG;
                    stg[(row0+8) * 128 + col]   = (s0 * (d2 - t0) > 0.f) ? POS : NEG;
                    stg[(row0+8) * 128 + col+1] = (s1 * (d3 - t1) > 0.f) ? POS : NEG;
                }
        }
        __syncthreads();
        for (int i = tid; i < 2048; i += 256) {
            int row = i >> 4, c = i & 15;
            uint4 v = *(const uint4*)(stg + row * 128 + c * 8);
            *(uint4*)(d_act2 + (size_t)(m0 + row) * NN + n0 + c * 8) = v;
        }
    } else {
        float* stf = (float*)(sm + 32768);
        if (khalf == 0) {
            #pragma unroll
            for (int mt = 0; mt < 4; mt++)
                #pragma unroll
                for (int nt = 0; nt < 8; nt++) {
                    int col = wn * 64 + nt * 8 + tig * 2;
                    int n = n0 + col;
                    float sa = d_s3[n], sb2 = d_s3[n+1], oa = d_o3[n], ob = d_o3[n+1];
                    int row0 = wm * 64 + mt * 16 + g;
                    uint32_t p0 = mrg[tile * 2048 + ((mt*8+nt)*2 + 0) * 32 + lane];
                    uint32_t p1 = mrg[tile * 2048 + ((mt*8+nt)*2 + 1) * 32 + lane];
                    float2 m0v = __half22float2(*(const __half2*)&Ch[mt][nt][0]);
                    float2 m1v = __half22float2(*(const __half2*)&Ch[mt][nt][1]);
                    float2 p0v = __half22float2(*(const __half2*)&p0);
                    float2 p1v = __half22float2(*(const __half2*)&p1);
                    stf[row0 * 128 + col]       = fminf(fmaxf(sa  * (m0v.x + p0v.x) + oa, -1.f), 1.f);
                    stf[row0 * 128 + col + 1]   = fminf(fmaxf(sb2 * (m0v.y + p0v.y) + ob, -1.f), 1.f);
                    stf[(row0+8) * 128 + col]   = fminf(fmaxf(sa  * (m1v.x + p1v.x) + oa, -1.f), 1.f);
                    stf[(row0+8) * 128 + col+1] = fminf(fmaxf(sb2 * (m1v.y + p1v.y) + ob, -1.f), 1.f);
                }
        }
        __syncthreads();
        for (int i = tid; i < 4096; i += 256) {
            int row = i >> 5, c = i & 31;
            uint4 v = *(const uint4*)(stf + row * 128 + c * 4);
            *(uint4*)(d_h3c + (size_t)(m0 + row) * NN + n0 + c * 4) = v;
        }
    }
}

// ---------------- fc4 + log_softmax ----------------
__global__ __launch_bounds__(256) void fc4_kernel(const float* __restrict__ w4,
                                                  const float* __restrict__ b4,
                                                  float* __restrict__ out) {
    __shared__ float ws[D4 * D3];
    int tid = threadIdx.x;
    for (int i = tid; i < D4 * D3; i += 256) ws[i] = w4[i];
    __syncthreads();
    int warp = tid >> 5, lane = tid & 31;
    int row = blockIdx.x * 8 + warp;
    const float* hh = d_h3c + (size_t)row * D3;
    float acc[D4];
    #pragma unroll
    for (int c = 0; c < D4; c++) acc[c] = 0.f;
    #pragma unroll 4
    for (int t = 0; t < D3 / 32; ++t) {
        int k = t * 32 + lane;
        float hv = hh[k];
        #pragma unroll
        for (int c = 0; c < D4; c++) acc[c] = fmaf(hv, ws[c * D3 + k], acc[c]);
    }
    #pragma unroll
    for (int c = 0; c < D4; c++)
        #pragma unroll
        for (int off = 16; off; off >>= 1)
            acc[c] += __shfl_xor_sync(0xffffffffu, acc[c], off);
    if (lane == 0) {
        float l[D4], mx = -1e30f;
        #pragma unroll
        for (int c = 0; c < D4; c++) { l[c] = acc[c] + b4[c]; mx = fmaxf(mx, l[c]); }
        float s = 0.f;
        #pragma unroll
        for (int c = 0; c < D4; c++) s += expf(l[c] - mx);
        float lse = mx + logf(s);
        #pragma unroll
        for (int c = 0; c < D4; c++) out[(size_t)row * D4 + c] = l[c] - lse;
    }
}

// ---------------- launch ----------------
extern "C" void kernel_launch(void* const* d_in, const int* in_sizes, int n_in,
                              void* d_out, int out_size) {
    const float* x   = (const float*)d_in[0];
    const float* w1  = (const float*)d_in[1];
    const float* b1  = (const float*)d_in[2];
    const float* w2  = (const float*)d_in[3];
    const float* b2  = (const float*)d_in[4];
    const float* w3  = (const float*)d_in[5];
    const float* b3  = (const float*)d_in[6];
    const float* w4  = (const float*)d_in[7];
    const float* b4  = (const float*)d_in[8];
    const float* g1  = (const float*)d_in[9];
    const float* be1 = (const float*)d_in[10];
    const float* m1  = (const float*)d_in[11];
    const float* v1  = (const float*)d_in[12];
    const float* g2  = (const float*)d_in[13];
    const float* be2 = (const float*)d_in[14];
    const float* m2  = (const float*)d_in[15];
    const float* v2  = (const float*)d_in[16];
    const float* g3  = (const float*)d_in[17];
    const float* be3 = (const float*)d_in[18];
    const float* m3  = (const float*)d_in[19];
    const float* v3  = (const float*)d_in[20];

    cudaFuncSetAttribute(gemm1k,     cudaFuncAttributeMaxDynamicSharedMemorySize, SMEMB);
    cudaFuncSetAttribute(bgemm_k<2>, cudaFuncAttributeMaxDynamicSharedMemorySize, SMEMB);
    cudaFuncSetAttribute(bgemm_k<3>, cudaFuncAttributeMaxDynamicSharedMemorySize, SMEMB);

    int nblk = (int)((NTOT4 + 255) / 256);
    prep_all<<<nblk, 256>>>(x, w1, w2, w3,
                            b1, g1, be1, m1, v1,
                            b2, g2, be2, m2, v2,
                            b3, g3, be3, m3, v3);
    gemm1k<<<dim3(D1 / 128, B_ / 128), 256, SMEMB>>>();
    repair1<<<1024, 128>>>(x, w1);
    bgemm_k<2><<<dim3(D2 / 128, B_ / 128), 256, SMEMB>>>();   // slot 4 -> profiled
    bgemm_k<3><<<dim3(D3 / 128, B_ / 128), 256, SMEMB>>>();
    fc4_kernel<<<B_ / 8, 256>>>(w4, b4, (float*)d_out);
}

// round 16
// speedup vs baseline: 1.5245x; 1.5245x over previous
#include <cuda_runtime.h>
#include <cuda_fp16.h>
#include <cstdint>

#define EPSBN 1e-5f
#define B_  16384
#define D0  784
#define K1  832
#define D1  3072
#define D2  1536
#define D3  768
#define D4  10
#define TAU 0.03f
#define FIXCAP (1 << 21)

__device__ __align__(128) __half d_A1[(size_t)B_*K1];
__device__ __align__(128) __half d_B1[(size_t)D1*K1];
__device__ __align__(128) __half d_B2[(size_t)D2*D1];
__device__ __align__(128) __half d_B3[(size_t)D3*D2];
__device__ __align__(128) __half d_act1[(size_t)B_*D1];
__device__ __align__(128) __half d_act2[(size_t)B_*D2];
__device__ __align__(128) float d_h3c[(size_t)B_*D3];
__device__ float d_thr1[D1], d_sg1[D1], d_thr2[D2], d_sg2[D2], d_s3[D3], d_o3[D3];
__device__ int d_fix_cnt;
__device__ int d_fix_list[FIXCAP];

__device__ __forceinline__ uint32_t smem_u32(const void* p) {
    uint32_t a;
    asm("{ .reg .u64 t; cvta.to.shared.u64 t, %1; cvt.u32.u64 %0, t; }" : "=r"(a) : "l"(p));
    return a;
}
#define CPA16(dst, src) asm volatile("cp.async.cg.shared.global [%0], [%1], 16;" :: "r"(dst), "l"(src) : "memory")
#define CPA_COMMIT()    asm volatile("cp.async.commit_group;" ::: "memory")
#define CPA_WAIT1()     asm volatile("cp.async.wait_group 1;" ::: "memory")

__device__ __forceinline__ void ldm4(uint32_t* r, uint32_t a) {
    asm volatile("ldmatrix.sync.aligned.m8n8.x4.shared.b16 {%0,%1,%2,%3}, [%4];"
                 : "=r"(r[0]), "=r"(r[1]), "=r"(r[2]), "=r"(r[3]) : "r"(a));
}
__device__ __forceinline__ void mma_f16(float* c, const uint32_t* a, const uint32_t* b) {
    asm volatile("mma.sync.aligned.m16n8k16.row.col.f32.f16.f16.f32 "
                 "{%0,%1,%2,%3}, {%4,%5,%6,%7}, {%8,%9}, {%0,%1,%2,%3};"
                 : "+f"(c[0]), "+f"(c[1]), "+f"(c[2]), "+f"(c[3])
                 : "r"(a[0]), "r"(a[1]), "r"(a[2]), "r"(a[3]), "r"(b[0]), "r"(b[1]));
}
// f16 accumulator: exact for integer sums |s| <= 2048
__device__ __forceinline__ void mma_f16h(uint32_t* c, const uint32_t* a, const uint32_t* b) {
    asm volatile("mma.sync.aligned.m16n8k16.row.col.f16.f16.f16.f16 "
                 "{%0,%1}, {%2,%3,%4,%5}, {%6,%7}, {%0,%1};"
                 : "+r"(c[0]), "+r"(c[1])
                 : "r"(a[0]), "r"(a[1]), "r"(a[2]), "r"(a[3]), "r"(b[0]), "r"(b[1]));
}

__device__ __forceinline__ float sgnf(float w) {
    return (w > 0.f) ? 1.f : ((w < 0.f) ? -1.f : 0.f);
}
__device__ __forceinline__ void st4h(__half* p, float a, float b, float c, float d) {
    __half2 lo = __floats2half2_rn(a, b);
    __half2 hi = __floats2half2_rn(c, d);
    uint2 u;
    u.x = *(uint32_t*)&lo;
    u.y = *(uint32_t*)&hi;
    *(uint2*)p = u;
}

// ---------------- merged prep, x4 vectorized (single launch) -------------
#define NA4   ((size_t)B_ * D0 / 4)
#define NPA4  ((size_t)B_ * (K1 - D0) / 4)
#define NB4   ((size_t)D1 * D0 / 4)
#define NPB4  ((size_t)D1 * (K1 - D0) / 4)
#define NW24  ((size_t)D2 * D1 / 4)
#define NW34  ((size_t)D3 * D2 / 4)
#define NTOT4 (NA4 + NPA4 + NB4 + NPB4 + NW24 + NW34 + D1)

__global__ void prep_all(const float* __restrict__ x,  const float* __restrict__ w1,
                         const float* __restrict__ w2, const float* __restrict__ w3,
    const float* __restrict__ b1, const float* __restrict__ g1, const float* __restrict__ be1,
    const float* __restrict__ m1, const float* __restrict__ v1,
    const float* __restrict__ b2, const float* __restrict__ g2, const float* __restrict__ be2,
    const float* __restrict__ m2, const float* __restrict__ v2,
    const float* __restrict__ b3, const float* __restrict__ g3, const float* __restrict__ be3,
    const float* __restrict__ m3, const float* __restrict__ v3)
{
    size_t idx = (size_t)blockIdx.x * 256 + threadIdx.x;
    if (idx == 0) d_fix_cnt = 0;
    if (idx < NA4) {
        int i = (int)(idx / (D0/4)), k4 = (int)(idx % (D0/4));
        float4 v = *(const float4*)(x + (size_t)i * D0 + k4 * 4);
        st4h(d_A1 + (size_t)i * K1 + k4 * 4, v.x, v.y, v.z, v.w);
    } else if (idx < NA4 + NPA4) {
        size_t t = idx - NA4;
        int i = (int)(t / 12), j = (int)(t % 12);
        st4h(d_A1 + (size_t)i * K1 + D0 + j * 4, 0.f, 0.f, 0.f, 0.f);
    } else if (idx < NA4 + NPA4 + NB4) {
        size_t t = idx - NA4 - NPA4;
        int i = (int)(t / (D0/4)), k4 = (int)(t % (D0/4));
        float4 v = *(const float4*)(w1 + (size_t)i * D0 + k4 * 4);
        st4h(d_B1 + (size_t)i * K1 + k4 * 4, sgnf(v.x), sgnf(v.y), sgnf(v.z), sgnf(v.w));
    } else if (idx < NA4 + NPA4 + NB4 + NPB4) {
        size_t t = idx - NA4 - NPA4 - NB4;
        int i = (int)(t / 12), j = (int)(t % 12);
        st4h(d_B1 + (size_t)i * K1 + D0 + j * 4, 0.f, 0.f, 0.f, 0.f);
    } else if (idx < NA4 + NPA4 + NB4 + NPB4 + NW24) {
        size_t t = (idx - NA4 - NPA4 - NB4 - NPB4) * 4;
        float4 v = *(const float4*)(w2 + t);
        st4h(d_B2 + t, sgnf(v.x), sgnf(v.y), sgnf(v.z), sgnf(v.w));
    } else if (idx < NA4 + NPA4 + NB4 + NPB4 + NW24 + NW34) {
        size_t t = (idx - NA4 - NPA4 - NB4 - NPB4 - NW24) * 4;
        float4 v = *(const float4*)(w3 + t);
        st4h(d_B3 + t, sgnf(v.x), sgnf(v.y), sgnf(v.z), sgnf(v.w));
    } else {
        int j = (int)(idx - (NA4 + NPA4 + NB4 + NPB4 + NW24 + NW34));
        if (j < D1) {
            float g = g1[j];
            d_thr1[j] = m1[j] - be1[j] * sqrtf(v1[j] + EPSBN) / g - b1[j];
            d_sg1[j]  = (g > 0.f) ? 1.f : -1.f;
        }
        if (j < D2) {
            float g = g2[j];
            d_thr2[j] = m2[j] - be2[j] * sqrtf(v2[j] + EPSBN) / g - b2[j];
            d_sg2[j]  = (g > 0.f) ? 1.f : -1.f;
        }
        if (j < D3) {
            float g = g3[j];
            float s = g / sqrtf(v3[j] + EPSBN);
            d_s3[j] = s;
            d_o3[j] = (b3[j] - m3[j]) * s + be3[j];
        }
    }
}

// ---------------- repair: warp-cooperative staging, exact sequential sum --
#define RWARPS 4
__global__ __launch_bounds__(128) void repair1(const float* __restrict__ x,
                                               const float* __restrict__ w1) {
    __shared__ float sx[RWARPS][D0];
    __shared__ float sw[RWARPS][D0];
    int cnt = d_fix_cnt; if (cnt > FIXCAP) cnt = FIXCAP;
    int warp = threadIdx.x >> 5, lane = threadIdx.x & 31;
    for (int i = blockIdx.x * RWARPS + warp; i < cnt; i += gridDim.x * RWARPS) {
        int e = d_fix_list[i];
        int m = e / D1, n = e % D1;
        const float* xr = x  + (size_t)m * D0;
        const float* wr = w1 + (size_t)n * D0;
        #pragma unroll 5
        for (int k = lane; k < D0; k += 32) {
            sx[warp][k] = xr[k];
            float w = wr[k];
            sw[warp][k] = (w > 0.f) ? 1.f : ((w < 0.f) ? -1.f : 0.f);
        }
        __syncwarp();
        if (lane == 0) {
            float acc = 0.f;
            for (int k = 0; k < D0; k++)
                acc = fmaf(sx[warp][k], sw[warp][k], acc);
            float f = d_sg1[n] * (acc - d_thr1[n]);
            d_act1[(size_t)m * D1 + n] = __float2half_rn((f > 0.f) ? 1.f : -1.f);
        }
        __syncwarp();
    }
}

// ---------------- fc1 GEMM: f32 acc, 128x128 CTA tile, 3-stage (R10) -----
#define SMEMB 98304

__global__ __launch_bounds__(256, 2) void gemm1k() {
    constexpr int NS = 13, KB = K1*2, NN = D1;
    extern __shared__ char sm[];
    uint32_t sb = smem_u32(sm);
    int tid = threadIdx.x, lane = tid & 31, wid = tid >> 5;
    int wm = wid & 3, wn = wid >> 2;
    int m0 = blockIdx.y * 128, n0 = blockIdx.x * 128;

    const char* gA = (const char*)d_A1;
    const char* gB = (const char*)d_B1;
    int r = tid >> 1, h = tid & 1;
    gA += (size_t)(m0 + r) * KB + h * 64;
    gB += (size_t)(n0 + r) * KB + h * 64;

    auto load = [&](int kt, int s) {
        uint32_t o = sb + s * 32768 + r * 128;
        size_t ko = (size_t)kt * 128;
        #pragma unroll
        for (int j = 0; j < 4; j++) {
            uint32_t sw = (uint32_t)(((h * 4 + j) ^ (r & 7)) << 4);
            CPA16(o + sw,         gA + ko + j * 16);
            CPA16(o + 16384 + sw, gB + ko + j * 16);
        }
    };

    float Cf[2][8][4];
    #pragma unroll
    for (int mt = 0; mt < 2; mt++)
        #pragma unroll
        for (int nt = 0; nt < 8; nt++)
            #pragma unroll
            for (int q = 0; q < 4; q++) Cf[mt][nt][q] = 0.f;

    load(0, 0); CPA_COMMIT();
    load(1, 1); CPA_COMMIT();

    int arow = wm * 32 + (lane & 15);
    int asel = lane >> 4;
    int brow = wn * 64 + (lane & 7) + ((lane >> 4) << 3);
    int bsel = (lane >> 3) & 1;

    for (int kt = 0; kt < NS; ++kt) {
        CPA_WAIT1();
        __syncthreads();
        uint32_t Ab = sb + (kt % 3) * 32768;
        uint32_t Bb = Ab + 16384;
        uint32_t a[2][2][4], b[2][4][4];
        #define LDFRAG(d, kk)                                                        \
            do {                                                                     \
                _Pragma("unroll")                                                    \
                for (int mt = 0; mt < 2; mt++) {                                     \
                    int rr = arow + mt * 16;                                         \
                    ldm4(a[d][mt], Ab + rr * 128 + ((((kk) * 2 + asel) ^ (rr & 7)) << 4)); \
                }                                                                    \
                _Pragma("unroll")                                                    \
                for (int q = 0; q < 4; q++) {                                        \
                    int nr = brow + q * 16;                                          \
                    ldm4(b[d][q], Bb + nr * 128 + ((((kk) * 2 + bsel) ^ (nr & 7)) << 4)); \
                }                                                                    \
            } while (0)
        LDFRAG(0, 0);
        #pragma unroll
        for (int kk = 0; kk < 4; kk++) {
            int cur = kk & 1;
            if (kk < 3) {
                LDFRAG(cur ^ 1, kk + 1);
            } else {
                if (kt + 2 < NS) load(kt + 2, (kt + 2) % 3);
                CPA_COMMIT();
            }
            #pragma unroll
            for (int mt = 0; mt < 2; mt++)
                #pragma unroll
                for (int q = 0; q < 4; q++) {
                    mma_f16(Cf[mt][2*q],     a[cur][mt], &b[cur][q][0]);
                    mma_f16(Cf[mt][2*q + 1], a[cur][mt], &b[cur][q][2]);
                }
        }
        #undef LDFRAG
    }
    __syncthreads();

    int g = lane >> 2, tig = lane & 3;
    const __half POS = __float2half_rn(1.f), NEG = __float2half_rn(-1.f);
    __half* stg = (__half*)sm;
    #pragma unroll
    for (int mt = 0; mt < 2; mt++)
        #pragma unroll
        for (int nt = 0; nt < 8; nt++) {
            int col = wn * 64 + nt * 8 + tig * 2;
            int n = n0 + col;
            float t0 = d_thr1[n], t1 = d_thr1[n+1], s0 = d_sg1[n], s1 = d_sg1[n+1];
            int row0 = wm * 32 + mt * 16 + g;
            float f0 = s0 * (Cf[mt][nt][0] - t0), f1 = s1 * (Cf[mt][nt][1] - t1);
            float f2 = s0 * (Cf[mt][nt][2] - t0), f3 = s1 * (Cf[mt][nt][3] - t1);
            stg[row0 * 128 + col]       = (f0 > 0.f) ? POS : NEG;
            stg[row0 * 128 + col + 1]   = (f1 > 0.f) ? POS : NEG;
            stg[(row0+8) * 128 + col]   = (f2 > 0.f) ? POS : NEG;
            stg[(row0+8) * 128 + col+1] = (f3 > 0.f) ? POS : NEG;
            if (fabsf(f0) < TAU) { int ix = atomicAdd(&d_fix_cnt, 1); if (ix < FIXCAP) d_fix_list[ix] = (m0+row0)   * D1 + n;   }
            if (fabsf(f1) < TAU) { int ix = atomicAdd(&d_fix_cnt, 1); if (ix < FIXCAP) d_fix_list[ix] = (m0+row0)   * D1 + n+1; }
            if (fabsf(f2) < TAU) { int ix = atomicAdd(&d_fix_cnt, 1); if (ix < FIXCAP) d_fix_list[ix] = (m0+row0+8) * D1 + n;   }
            if (fabsf(f3) < TAU) { int ix = atomicAdd(&d_fix_cnt, 1); if (ix < FIXCAP) d_fix_list[ix] = (m0+row0+8) * D1 + n+1; }
        }
    __syncthreads();
    for (int i = tid; i < 2048; i += 256) {
        int row = i >> 4, c = i & 15;
        uint4 v = *(const uint4*)(stg + row * 128 + c * 8);
        *(uint4*)(d_act1 + (size_t)(m0 + row) * NN + n0 + c * 8) = v;
    }
}

// ---------------- fc2/fc3: K-split f16-acc GEMM, CTA 128x128 (R13) -------
template <int LAYER>
__global__ __launch_bounds__(256, 2) void bgemm_k() {
    constexpr int NS = (LAYER == 2) ? 48 : 24;
    constexpr int KB = (LAYER == 2) ? D1*2 : D2*2;
    constexpr int NN = (LAYER == 2) ? D2 : D3;

    extern __shared__ char sm[];
    uint32_t sb = smem_u32(sm);
    int tid = threadIdx.x, lane = tid & 31, wid = tid >> 5;
    int tile = wid & 3, khalf = wid >> 2;
    int wm = tile & 1, wn = tile >> 1;
    int m0 = blockIdx.y * 128, n0 = blockIdx.x * 128;

    const char* gA = (LAYER == 2) ? (const char*)d_act1 : (const char*)d_act2;
    const char* gB = (LAYER == 2) ? (const char*)d_B2   : (const char*)d_B3;
    int r = tid >> 1, h = tid & 1;
    gA += (size_t)(m0 + r) * KB + h * 64;
    gB += (size_t)(n0 + r) * KB + h * 64;

    auto load = [&](int kt, int s) {
        uint32_t o = sb + s * 32768 + r * 128;
        size_t ko = (size_t)kt * 128;
        #pragma unroll
        for (int j = 0; j < 4; j++) {
            uint32_t sw = (uint32_t)(((h * 4 + j) ^ (r & 7)) << 4);
            CPA16(o + sw,         gA + ko + j * 16);
            CPA16(o + 16384 + sw, gB + ko + j * 16);
        }
    };

    uint32_t Ch[4][8][2];
    #pragma unroll
    for (int mt = 0; mt < 4; mt++)
        #pragma unroll
        for (int nt = 0; nt < 8; nt++) { Ch[mt][nt][0] = 0u; Ch[mt][nt][1] = 0u; }

    load(0, 0); CPA_COMMIT();
    load(1, 1); CPA_COMMIT();

    int arow = wm * 64 + (lane & 15);
    int asel = lane >> 4;
    int brow = wn * 64 + (lane & 7) + ((lane >> 4) << 3);
    int bsel = (lane >> 3) & 1;

    for (int kt = 0; kt < NS; ++kt) {
        CPA_WAIT1();
        __syncthreads();
        uint32_t Ab = sb + (kt % 3) * 32768;
        uint32_t Bb = Ab + 16384;
        #pragma unroll
        for (int k2 = 0; k2 < 2; k2++) {
            int kk = khalf * 2 + k2;
            uint32_t a[4][4], b[4][4];
            #pragma unroll
            for (int mt = 0; mt < 4; mt++) {
                int rr = arow + mt * 16;
                ldm4(a[mt], Ab + rr * 128 + (((kk * 2 + asel) ^ (rr & 7)) << 4));
            }
            #pragma unroll
            for (int q = 0; q < 4; q++) {
                int nr = brow + q * 16;
                ldm4(b[q], Bb + nr * 128 + (((kk * 2 + bsel) ^ (nr & 7)) << 4));
            }
            if (k2 == 1) {
                if (kt + 2 < NS) load(kt + 2, (kt + 2) % 3);
                CPA_COMMIT();
            }
            #pragma unroll
            for (int mt = 0; mt < 4; mt++)
                #pragma unroll
                for (int q = 0; q < 4; q++) {
                    mma_f16h(Ch[mt][2*q],     a[mt], &b[q][0]);
                    mma_f16h(Ch[mt][2*q + 1], a[mt], &b[q][2]);
                }
        }
    }
    __syncthreads();   // pipeline smem dead; reuse

    // merge: khalf=1 warps dump partials (32KB at sm+0)
    uint32_t* mrg = (uint32_t*)sm;
    if (khalf == 1) {
        #pragma unroll
        for (int mt = 0; mt < 4; mt++)
            #pragma unroll
            for (int nt = 0; nt < 8; nt++) {
                mrg[tile * 2048 + ((mt*8+nt)*2 + 0) * 32 + lane] = Ch[mt][nt][0];
                mrg[tile * 2048 + ((mt*8+nt)*2 + 1) * 32 + lane] = Ch[mt][nt][1];
            }
    }
    __syncthreads();

    int g = lane >> 2, tig = lane & 3;
    if constexpr (LAYER == 2) {
        const __half POS = __float2half_rn(1.f), NEG = __float2half_rn(-1.f);
        __half* stg = (__half*)(sm + 32768);
        if (khalf == 0) {
            #pragma unroll
            for (int mt = 0; mt < 4; mt++)
                #pragma unroll
                for (int nt = 0; nt < 8; nt++) {
                    int col = wn * 64 + nt * 8 + tig * 2;
                    int n = n0 + col;
                    float t0 = d_thr2[n], t1 = d_thr2[n+1], s0 = d_sg2[n], s1 = d_sg2[n+1];
                    int row0 = wm * 64 + mt * 16 + g;
                    uint32_t p0 = mrg[tile * 2048 + ((mt*8+nt)*2 + 0) * 32 + lane];
                    uint32_t p1 = mrg[tile * 2048 + ((mt*8+nt)*2 + 1) * 32 + lane];
                    float2 m0v = __half22float2(*(const __half2*)&Ch[mt][nt][0]);
                    float2 m1v = __half22float2(*(const __half2*)&Ch[mt][nt][1]);
                    float2 p0v = __half22float2(*(const __half2*)&p0);
                    float2 p1v = __half22float2(*(const __half2*)&p1);
                    float d0 = m0v.x + p0v.x, d1 = m0v.y + p0v.y;
                    float d2 = m1v.x + p1v.x, d3 = m1v.y + p1v.y;
                    stg[row0 * 128 + col]       = (s0 * (d0 - t0) > 0.f) ? POS : NEG;
                    stg[row0 * 128 + col + 1]   = (s1 * (d1 - t1) > 0.f) ? POS : NEG;
                    stg[(row0+8) * 128 + col]   = (s0 * (d2 - t0) > 0.f) ? POS : NEG;
                    stg[(row0+8) * 128 + col+1] = (s1 * (d3 - t1) > 0.f) ? POS : NEG;
                }
        }
        __syncthreads();
        for (int i = tid; i < 2048; i += 256) {
            int row = i >> 4, c = i & 15;
            uint4 v = *(const uint4*)(stg + row * 128 + c * 8);
            *(uint4*)(d_act2 + (size_t)(m0 + row) * NN + n0 + c * 8) = v;
        }
    } else {
        float* stf = (float*)(sm + 32768);
        if (khalf == 0) {
            #pragma unroll
            for (int mt = 0; mt < 4; mt++)
                #pragma unroll
                for (int nt = 0; nt < 8; nt++) {
                    int col = wn * 64 + nt * 8 + tig * 2;
                    int n = n0 + col;
                    float sa = d_s3[n], sb2 = d_s3[n+1], oa = d_o3[n], ob = d_o3[n+1];
                    int row0 = wm * 64 + mt * 16 + g;
                    uint32_t p0 = mrg[tile * 2048 + ((mt*8+nt)*2 + 0) * 32 + lane];
                    uint32_t p1 = mrg[tile * 2048 + ((mt*8+nt)*2 + 1) * 32 + lane];
                    float2 m0v = __half22float2(*(const __half2*)&Ch[mt][nt][0]);
                    float2 m1v = __half22float2(*(const __half2*)&Ch[mt][nt][1]);
                    float2 p0v = __half22float2(*(const __half2*)&p0);
                    float2 p1v = __half22float2(*(const __half2*)&p1);
                    stf[row0 * 128 + col]       = fminf(fmaxf(sa  * (m0v.x + p0v.x) + oa, -1.f), 1.f);
                    stf[row0 * 128 + col + 1]   = fminf(fmaxf(sb2 * (m0v.y + p0v.y) + ob, -1.f), 1.f);
                    stf[(row0+8) * 128 + col]   = fminf(fmaxf(sa  * (m1v.x + p1v.x) + oa, -1.f), 1.f);
                    stf[(row0+8) * 128 + col+1] = fminf(fmaxf(sb2 * (m1v.y + p1v.y) + ob, -1.f), 1.f);
                }
        }
        __syncthreads();
        for (int i = tid; i < 4096; i += 256) {
            int row = i >> 5, c = i & 31;
            uint4 v = *(const uint4*)(stf + row * 128 + c * 4);
            *(uint4*)(d_h3c + (size_t)(m0 + row) * NN + n0 + c * 4) = v;
        }
    }
}

// ---------------- fc4 + log_softmax ----------------
__global__ __launch_bounds__(256) void fc4_kernel(const float* __restrict__ w4,
                                                  const float* __restrict__ b4,
                                                  float* __restrict__ out) {
    __shared__ float ws[D4 * D3];
    int tid = threadIdx.x;
    for (int i = tid; i < D4 * D3; i += 256) ws[i] = w4[i];
    __syncthreads();
    int warp = tid >> 5, lane = tid & 31;
    int row = blockIdx.x * 8 + warp;
    const float* hh = d_h3c + (size_t)row * D3;
    float acc[D4];
    #pragma unroll
    for (int c = 0; c < D4; c++) acc[c] = 0.f;
    #pragma unroll 4
    for (int t = 0; t < D3 / 32; ++t) {
        int k = t * 32 + lane;
        float hv = hh[k];
        #pragma unroll
        for (int c = 0; c < D4; c++) acc[c] = fmaf(hv, ws[c * D3 + k], acc[c]);
    }
    #pragma unroll
    for (int c = 0; c < D4; c++)
        #pragma unroll
        for (int off = 16; off; off >>= 1)
            acc[c] += __shfl_xor_sync(0xffffffffu, acc[c], off);
    if (lane == 0) {
        float l[D4], mx = -1e30f;
        #pragma unroll
        for (int c = 0; c < D4; c++) { l[c] = acc[c] + b4[c]; mx = fmaxf(mx, l[c]); }
        float s = 0.f;
        #pragma unroll
        for (int c = 0; c < D4; c++) s += expf(l[c] - mx);
        float lse = mx + logf(s);
        #pragma unroll
        for (int c = 0; c < D4; c++) out[(size_t)row * D4 + c] = l[c] - lse;
    }
}

// ---------------- launch ----------------
extern "C" void kernel_launch(void* const* d_in, const int* in_sizes, int n_in,
                              void* d_out, int out_size) {
    const float* x   = (const float*)d_in[0];
    const float* w1  = (const float*)d_in[1];
    const float* b1  = (const float*)d_in[2];
    const float* w2  = (const float*)d_in[3];
    const float* b2  = (const float*)d_in[4];
    const float* w3  = (const float*)d_in[5];
    const float* b3  = (const float*)d_in[6];
    const float* w4  = (const float*)d_in[7];
    const float* b4  = (const float*)d_in[8];
    const float* g1  = (const float*)d_in[9];
    const float* be1 = (const float*)d_in[10];
    const float* m1  = (const float*)d_in[11];
    const float* v1  = (const float*)d_in[12];
    const float* g2  = (const float*)d_in[13];
    const float* be2 = (const float*)d_in[14];
    const float* m2  = (const float*)d_in[15];
    const float* v2  = (const float*)d_in[16];
    const float* g3  = (const float*)d_in[17];
    const float* be3 = (const float*)d_in[18];
    const float* m3  = (const float*)d_in[19];
    const float* v3  = (const float*)d_in[20];

    cudaFuncSetAttribute(gemm1k,     cudaFuncAttributeMaxDynamicSharedMemorySize, SMEMB);
    cudaFuncSetAttribute(bgemm_k<2>, cudaFuncAttributeMaxDynamicSharedMemorySize, SMEMB);
    cudaFuncSetAttribute(bgemm_k<3>, cudaFuncAttributeMaxDynamicSharedMemorySize, SMEMB);

    int nblk = (int)((NTOT4 + 255) / 256);
    prep_all<<<nblk, 256>>>(x, w1, w2, w3,
                            b1, g1, be1, m1, v1,
                            b2, g2, be2, m2, v2,
                            b3, g3, be3, m3, v3);
    gemm1k<<<dim3(D1 / 128, B_ / 128), 256, SMEMB>>>();
    repair1<<<592, 128>>>(x, w1);
    bgemm_k<2><<<dim3(D2 / 128, B_ / 128), 256, SMEMB>>>();   // slot 4 -> profiled
    bgemm_k<3><<<dim3(D3 / 128, B_ / 128), 256, SMEMB>>>();
    fc4_kernel<<<B_ / 8, 256>>>(w4, b4, (float*)d_out);
}